// round 10
// baseline (speedup 1.0000x reference)
#include <cuda_runtime.h>
#include <math.h>

#define T_  512
#define B_  64
#define E_  256
#define H_  256
#define TB_ (T_ * B_)          // 32768
#define CLU 8                  // CTAs per cluster
#define BGR 8                  // batch elements per cluster (two quads)

// ---------------- static device scratch ----------------
__device__ float g_Q  [TB_ * E_];
__device__ float g_K  [TB_ * E_];
__device__ float g_S  [B_ * T_ * T_];
__device__ float g_CTX[TB_ * E_];
__device__ float g_CP [TB_ * H_];
__device__ float g_PRE[(long)TB_ * 4 * H_];
__device__ float g_Wall[512 * 1024];       // packed [Wf|Wi|Wu|Wo] as (512, 1024)
__device__ float g_ball[1024];
__device__ float g_WhC[CLU * 256 * 32 * 4];// recurrent W: [rank][k][jl][gate4]

// ---------------- bf16 2-split helpers ----------------
__device__ __forceinline__ void split_bf2(float e, float o, unsigned& hi, unsigned& lo)
{
    unsigned h;
    asm("cvt.rn.bf16x2.f32 %0, %1, %2;" : "=r"(h) : "f"(o), "f"(e));
    float eh = __uint_as_float(h << 16);
    float oh = __uint_as_float(h & 0xffff0000u);
    unsigned l;
    asm("cvt.rn.bf16x2.f32 %0, %1, %2;" : "=r"(l) : "f"(o - oh), "f"(e - eh));
    hi = h; lo = l;
}

#define MMA_BF16(c, a, b)                                                          \
    asm volatile("mma.sync.aligned.m16n8k16.row.col.f32.bf16.bf16.f32 "            \
                 "{%0,%1,%2,%3},{%4,%5,%6,%7},{%8,%9},{%0,%1,%2,%3};"              \
                 : "+f"(c[0]), "+f"(c[1]), "+f"(c[2]), "+f"(c[3])                  \
                 : "r"(a[0]), "r"(a[1]), "r"(a[2]), "r"(a[3]),                     \
                   "r"(b[0]), "r"(b[1]))

// ---------------- tensor-core bf16 GEMM, 128x128x16 tile, 3x split, occ 2 ----
// (proven R8 version: single smem buffer, register prefetch)
template<bool NT, bool BIAS, bool CONCAT>
__global__ void __launch_bounds__(256, 2) gemm_tc(
    const float* __restrict__ A, const float* __restrict__ A2,
    const float* __restrict__ B, float* __restrict__ C,
    const float* __restrict__ bias,
    int M, int N, int K, int lda, int ldb, int ldc,
    long sA, long sB, long sC)
{
    A += (long)blockIdx.z * sA;
    B += (long)blockIdx.z * sB;
    C += (long)blockIdx.z * sC;

    __shared__ unsigned As_hi[8][136], As_lo[8][136];
    __shared__ unsigned Bs_hi[8][136], Bs_lo[8][136];

    const int tid  = threadIdx.x;
    const int lane = tid & 31;
    const int warp = tid >> 5;
    const int m0 = blockIdx.y * 128;
    const int n0 = blockIdx.x * 128;
    const int wm = (warp >> 2) * 64;
    const int wn = (warp & 3) * 32;
    const int gq = lane >> 2;
    const int tg = lane & 3;

    const int ar = tid & 127;
    const int aq = (tid >> 7) * 4;
    const int bkr = tid >> 5;
    const int bn  = (tid & 31) * 4;
    const int bn_t = tid & 127;
    const int bq   = (tid >> 7) * 4;

    float acc[4][4][4];
    #pragma unroll
    for (int i = 0; i < 4; ++i)
        #pragma unroll
        for (int j = 0; j < 4; ++j)
            #pragma unroll
            for (int q = 0; q < 4; ++q) acc[i][j][q] = 0.f;

    float4 va0, va1, vb0, vb1;
    auto load_tile = [&](int k0) {
        const float* Ab = A;
        int kc = k0;
        if (CONCAT) { if (k0 >= 256) { Ab = A2; kc = k0 - 256; } }
        va0 = *(const float4*)(Ab + (long)(m0 + ar) * lda + kc + aq);
        va1 = *(const float4*)(Ab + (long)(m0 + ar) * lda + kc + aq + 8);
        if (NT) {
            vb0 = *(const float4*)(B + (long)(n0 + bn_t) * ldb + k0 + bq);
            vb1 = *(const float4*)(B + (long)(n0 + bn_t) * ldb + k0 + bq + 8);
        } else {
            vb0 = *(const float4*)(B + (long)(k0 + 2 * bkr) * ldb + n0 + bn);
            vb1 = *(const float4*)(B + (long)(k0 + 2 * bkr + 1) * ldb + n0 + bn);
        }
    };

    load_tile(0);

    for (int k0 = 0; k0 < K; k0 += 16) {
        __syncthreads();
        {
            int kp = aq >> 1;
            split_bf2(va0.x, va0.y, As_hi[kp    ][ar], As_lo[kp    ][ar]);
            split_bf2(va0.z, va0.w, As_hi[kp + 1][ar], As_lo[kp + 1][ar]);
            split_bf2(va1.x, va1.y, As_hi[kp + 4][ar], As_lo[kp + 4][ar]);
            split_bf2(va1.z, va1.w, As_hi[kp + 5][ar], As_lo[kp + 5][ar]);
            if (NT) {
                int bp = bq >> 1;
                split_bf2(vb0.x, vb0.y, Bs_hi[bp    ][bn_t], Bs_lo[bp    ][bn_t]);
                split_bf2(vb0.z, vb0.w, Bs_hi[bp + 1][bn_t], Bs_lo[bp + 1][bn_t]);
                split_bf2(vb1.x, vb1.y, Bs_hi[bp + 4][bn_t], Bs_lo[bp + 4][bn_t]);
                split_bf2(vb1.z, vb1.w, Bs_hi[bp + 5][bn_t], Bs_lo[bp + 5][bn_t]);
            } else {
                uint4 h4, l4;
                split_bf2(vb0.x, vb1.x, h4.x, l4.x);
                split_bf2(vb0.y, vb1.y, h4.y, l4.y);
                split_bf2(vb0.z, vb1.z, h4.z, l4.z);
                split_bf2(vb0.w, vb1.w, h4.w, l4.w);
                *(uint4*)&Bs_hi[bkr][bn] = h4;
                *(uint4*)&Bs_lo[bkr][bn] = l4;
            }
        }
        __syncthreads();

        int kn = (k0 + 16 < K) ? k0 + 16 : k0;
        load_tile(kn);

        unsigned ah[4][4], al[4][4], bh[4][2], bl[4][2];
        #pragma unroll
        for (int i = 0; i < 4; ++i) {
            int r = wm + i * 16 + gq;
            ah[i][0] = As_hi[tg    ][r];
            ah[i][1] = As_hi[tg    ][r + 8];
            ah[i][2] = As_hi[tg + 4][r];
            ah[i][3] = As_hi[tg + 4][r + 8];
            al[i][0] = As_lo[tg    ][r];
            al[i][1] = As_lo[tg    ][r + 8];
            al[i][2] = As_lo[tg + 4][r];
            al[i][3] = As_lo[tg + 4][r + 8];
        }
        #pragma unroll
        for (int j = 0; j < 4; ++j) {
            int n = wn + j * 8 + gq;
            bh[j][0] = Bs_hi[tg    ][n];
            bh[j][1] = Bs_hi[tg + 4][n];
            bl[j][0] = Bs_lo[tg    ][n];
            bl[j][1] = Bs_lo[tg + 4][n];
        }
        #pragma unroll
        for (int i = 0; i < 4; ++i)
            #pragma unroll
            for (int j = 0; j < 4; ++j) {
                MMA_BF16(acc[i][j], ah[i], bh[j]);
                MMA_BF16(acc[i][j], al[i], bh[j]);
                MMA_BF16(acc[i][j], ah[i], bl[j]);
            }
    }

    #pragma unroll
    for (int i = 0; i < 4; ++i)
        #pragma unroll
        for (int j = 0; j < 4; ++j) {
            int m = m0 + wm + i * 16 + gq;
            int n = n0 + wn + j * 8 + 2 * tg;
            float2 v0 = make_float2(acc[i][j][0], acc[i][j][1]);
            float2 v1 = make_float2(acc[i][j][2], acc[i][j][3]);
            if (BIAS) {
                float b0 = bias[n], b1 = bias[n + 1];
                v0.x += b0; v0.y += b1;
                v1.x += b0; v1.y += b1;
            }
            *(float2*)(C + (long)m * ldc + n)       = v0;
            *(float2*)(C + (long)(m + 8) * ldc + n) = v1;
        }
}

// ---------------- softmax over rows of length 512 ----------
__global__ void __launch_bounds__(128) softmax_k(float* __restrict__ S)
{
    float* p = S + (long)blockIdx.x * 512;
    int tid = threadIdx.x;
    float v[4];
    float m = -1e30f;
    #pragma unroll
    for (int i = 0; i < 4; ++i) { v[i] = p[tid + 128 * i] * 0.0625f; m = fmaxf(m, v[i]); }
    __shared__ float red[128];
    red[tid] = m; __syncthreads();
    for (int s = 64; s > 0; s >>= 1) { if (tid < s) red[tid] = fmaxf(red[tid], red[tid + s]); __syncthreads(); }
    m = red[0]; __syncthreads();
    float sum = 0.f;
    #pragma unroll
    for (int i = 0; i < 4; ++i) { v[i] = expf(v[i] - m); sum += v[i]; }
    red[tid] = sum; __syncthreads();
    for (int s = 64; s > 0; s >>= 1) { if (tid < s) red[tid] += red[tid + s]; __syncthreads(); }
    float inv = 1.f / red[0];
    #pragma unroll
    for (int i = 0; i < 4; ++i) p[tid + 128 * i] = v[i] * inv;
}

// ---------------- pack weights ----------------
__global__ void pack_init_k(const float* __restrict__ Wf, const float* __restrict__ Wi,
                            const float* __restrict__ Wu, const float* __restrict__ Wo,
                            const float* __restrict__ bf, const float* __restrict__ bi,
                            const float* __restrict__ bu, const float* __restrict__ bo)
{
    int idx = blockIdx.x * blockDim.x + threadIdx.x;
    int nt = gridDim.x * blockDim.x;
    for (int i = idx; i < CLU * 256 * 32 * 4; i += nt) {
        int r  = i >> 15;
        int k  = (i >> 7) & 255;
        int jl = (i >> 2) & 31;
        int g  = i & 3;
        const float* W = (g == 0) ? Wf : (g == 1) ? Wi : (g == 2) ? Wu : Wo;
        g_WhC[i] = W[(E_ + k) * H_ + r * 32 + jl];
    }
    for (int i = idx; i < 512 * 1024; i += nt) {
        int k = i >> 10;
        int col = i & 1023;
        int g = col >> 8, j = col & 255;
        const float* W = (g == 0) ? Wf : (g == 1) ? Wi : (g == 2) ? Wu : Wo;
        g_Wall[i] = W[k * 256 + j];
    }
    for (int i = idx; i < 1024; i += nt) {
        int g = i >> 8;
        const float* b = (g == 0) ? bf : (g == 1) ? bi : (g == 2) ? bu : bo;
        g_ball[i] = b[i & 255];
    }
}

__device__ __forceinline__ float sigf(float x)  { return 1.f / (1.f + __expf(-x)); }
__device__ __forceinline__ float tanhf_(float x){ return 2.f / (1.f + __expf(-2.f * x)) - 1.f; }

#define CARRIVE() asm volatile("barrier.cluster.arrive.aligned;" ::: "memory")
#define CWAIT()   asm volatile("barrier.cluster.wait.aligned;"   ::: "memory")

// ---------- cluster LSTM recurrence: fused quads, parallel epilogue ----------
// Per step: [fused compute A+B, shared wv] [sync] [256-thread epi: 0-127=A,
// 128-255=B; conflict-free reduce eb=tid>>5, ejl=tid&31] [arrive; wait].
__global__ void __launch_bounds__(256, 1) __cluster_dims__(CLU, 1, 1)
recur7_k(const float* __restrict__ PRE, float* __restrict__ out)
{
    extern __shared__ float4 sm4[];
    float4* ws4   = sm4;            // [256 k][32 jl] gate4     8192 fl4
    float4* hsA   = sm4 + 8192;     // [2 buf][256 j] b4         512 fl4
    float4* hsB   = sm4 + 8704;     // [2 buf][256 j] b4         512 fl4
    float4* partA = sm4 + 9216;     // 4*257 = 1028 fl4
    float4* partB = sm4 + 10244;    // 4*257 = 1028 fl4

    const int tid = threadIdx.x;
    unsigned rank;
    asm("mov.u32 %0, %%cluster_ctarank;" : "=r"(rank));
    const int bg0 = (blockIdx.x >> 3) * BGR;

    const float4* Wsrc = (const float4*)g_WhC + (long)rank * 8192;
    for (int m = tid; m < 8192; m += 256) ws4[m] = Wsrc[m];
    for (int m = tid; m < 512; m += 256) {
        hsA[m] = make_float4(0.f, 0.f, 0.f, 0.f);
        hsB[m] = make_float4(0.f, 0.f, 0.f, 0.f);
    }

    const int jl = tid & 31;        // lane
    const int ks = tid >> 5;        // warp 0..7

    // epilogue mapping: first 128 threads -> quad A, rest -> quad B
    const bool qA   = tid < 128;
    const int  tid2 = tid & 127;
    const int  eb   = tid2 >> 5;    // 0..3 (warp-uniform)
    const int  ejl  = tid2 & 31;    // lane -> consecutive smem/out
    const int  jg   = rank * 32 + ejl;
    const int  bglob = bg0 + (qA ? 0 : 4) + eb;

    float creg = 0.f, hreg = 0.f;
    float p0 = 0.f, p1 = 0.f, p2 = 0.f, p3 = 0.f;
    {
        const float* pp = PRE + ((long)0 * B_ + bglob) * 1024 + jg;
        p0 = pp[0]; p1 = pp[256]; p2 = pp[512]; p3 = pp[768];
    }
    float4* mypart = qA ? partA : partB;
    const unsigned myhs_u32 = (unsigned)__cvta_generic_to_shared(qA ? hsA : hsB);

    __syncthreads();
    CARRIVE(); CWAIT();

    for (int t = 0; t < T_; ++t) {
        const int buf = t & 1;

        // ---------- fused compute: both quads, shared wv ----------
        {
            const float4* hpA = hsA + buf * 256 + ks * 32;
            const float4* hpB = hsB + buf * 256 + ks * 32;
            const float4* wp  = ws4 + (ks * 32) * 32 + jl;
            float4 aA0 = {0,0,0,0}, aA1 = {0,0,0,0}, aA2 = {0,0,0,0}, aA3 = {0,0,0,0};
            float4 aB0 = {0,0,0,0}, aB1 = {0,0,0,0}, aB2 = {0,0,0,0}, aB3 = {0,0,0,0};
            #pragma unroll 8
            for (int u = 0; u < 32; ++u) {
                float4 wv = wp[u * 32];
                float4 hA = hpA[u];
                float4 hB = hpB[u];
                aA0.x += hA.x*wv.x; aA0.y += hA.x*wv.y; aA0.z += hA.x*wv.z; aA0.w += hA.x*wv.w;
                aA1.x += hA.y*wv.x; aA1.y += hA.y*wv.y; aA1.z += hA.y*wv.z; aA1.w += hA.y*wv.w;
                aA2.x += hA.z*wv.x; aA2.y += hA.z*wv.y; aA2.z += hA.z*wv.z; aA2.w += hA.z*wv.w;
                aA3.x += hA.w*wv.x; aA3.y += hA.w*wv.y; aA3.z += hA.w*wv.z; aA3.w += hA.w*wv.w;
                aB0.x += hB.x*wv.x; aB0.y += hB.x*wv.y; aB0.z += hB.x*wv.z; aB0.w += hB.x*wv.w;
                aB1.x += hB.y*wv.x; aB1.y += hB.y*wv.y; aB1.z += hB.y*wv.z; aB1.w += hB.y*wv.w;
                aB2.x += hB.z*wv.x; aB2.y += hB.z*wv.y; aB2.z += hB.z*wv.z; aB2.w += hB.z*wv.w;
                aB3.x += hB.w*wv.x; aB3.y += hB.w*wv.y; aB3.z += hB.w*wv.z; aB3.w += hB.w*wv.w;
            }
            partA[0 * 257 + ks * 32 + jl] = aA0;
            partA[1 * 257 + ks * 32 + jl] = aA1;
            partA[2 * 257 + ks * 32 + jl] = aA2;
            partA[3 * 257 + ks * 32 + jl] = aA3;
            partB[0 * 257 + ks * 32 + jl] = aB0;
            partB[1 * 257 + ks * 32 + jl] = aB1;
            partB[2 * 257 + ks * 32 + jl] = aB2;
            partB[3 * 257 + ks * 32 + jl] = aB3;
        }
        __syncthreads();

        // ---------- parallel epilogue: all 256 threads ----------
        {
            float4 s = mypart[eb * 257 + 0 * 32 + ejl];
            #pragma unroll
            for (int q = 1; q < 8; ++q) {
                float4 p = mypart[eb * 257 + q * 32 + ejl];
                s.x += p.x; s.y += p.y; s.z += p.z; s.w += p.w;
            }
            float fg = sigf  (s.x + p0);
            float ig = sigf  (s.y + p1);
            float ug = tanhf_(s.z + p2);
            float og = sigf  (s.w + p3);
            creg = fg * creg + ig * ug;
            hreg = og * tanhf_(creg);
            out[((long)t * B_ + bglob) * H_ + jg] = hreg;

            unsigned laddr = myhs_u32 + ((((buf ^ 1) * 256 + jg) * 4 + eb) << 2);
            #pragma unroll
            for (int r2 = 0; r2 < CLU; ++r2) {
                unsigned ra;
                asm volatile("mapa.shared::cluster.u32 %0, %1, %2;"
                             : "=r"(ra) : "r"(laddr), "r"(r2));
                asm volatile("st.shared::cluster.f32 [%0], %1;"
                             :: "r"(ra), "f"(hreg) : "memory");
            }
            int tn = (t < T_ - 1) ? t + 1 : t;
            const float* pp = PRE + ((long)tn * B_ + bglob) * 1024 + jg;
            p0 = pp[0]; p1 = pp[256]; p2 = pp[512]; p3 = pp[768];
        }

        CARRIVE();
        CWAIT();
    }

    out[(long)TB_ * H_ + bglob * H_ + jg] = hreg;                 // hx
    out[(long)TB_ * H_ + (long)B_ * H_ + bglob * H_ + jg] = creg; // cx
}

// ---------------- launch ----------------
extern "C" void kernel_launch(void* const* d_in, const int* in_sizes, int n_in,
                              void* d_out, int out_size)
{
    const float* inputs = (const float*)d_in[0];
    const float* rot    = (const float*)d_in[1];
    const float* ent    = (const float*)d_in[2];
    const float* Wf = (const float*)d_in[3];  const float* bf = (const float*)d_in[4];
    const float* Wi = (const float*)d_in[5];  const float* bi = (const float*)d_in[6];
    const float* Wu = (const float*)d_in[7];  const float* bu = (const float*)d_in[8];
    const float* Wo = (const float*)d_in[9];  const float* bo = (const float*)d_in[10];
    const float* Wc = (const float*)d_in[11]; const float* bc = (const float*)d_in[12];
    float* out = (float*)d_out;

    float *Q, *K, *S, *CTX, *CP, *PRE, *Wall, *ball;
    cudaGetSymbolAddress((void**)&Q,    g_Q);
    cudaGetSymbolAddress((void**)&K,    g_K);
    cudaGetSymbolAddress((void**)&S,    g_S);
    cudaGetSymbolAddress((void**)&CTX,  g_CTX);
    cudaGetSymbolAddress((void**)&CP,   g_CP);
    cudaGetSymbolAddress((void**)&PRE,  g_PRE);
    cudaGetSymbolAddress((void**)&Wall, g_Wall);
    cudaGetSymbolAddress((void**)&ball, g_ball);

    const int RSMEM = (8192 + 512 + 512 + 1028 + 1028) * 16;   // 180352 B
    cudaFuncSetAttribute(recur7_k, cudaFuncAttributeMaxDynamicSharedMemorySize, RSMEM);

    pack_init_k<<<256, 256>>>(Wf, Wi, Wu, Wo, bf, bi, bu, bo);

    // Q = X @ rot ; K = X @ ent
    gemm_tc<false, false, false><<<dim3(E_ / 128, TB_ / 128, 1), 256>>>(
        inputs, nullptr, rot, Q, nullptr, TB_, E_, E_, E_, E_, E_, 0, 0, 0);
    gemm_tc<false, false, false><<<dim3(E_ / 128, TB_ / 128, 1), 256>>>(
        inputs, nullptr, ent, K, nullptr, TB_, E_, E_, E_, E_, E_, 0, 0, 0);

    // scores_b = Q_b @ K_b^T
    gemm_tc<true, false, false><<<dim3(T_ / 128, T_ / 128, B_), 256>>>(
        Q, nullptr, K, S, nullptr, T_, T_, E_, B_ * E_, B_ * E_, T_,
        (long)E_, (long)E_, (long)T_ * T_);

    softmax_k<<<B_ * T_, 128>>>(S);

    // context_b = S_b @ X_b
    gemm_tc<false, false, false><<<dim3(E_ / 128, T_ / 128, B_), 256>>>(
        S, nullptr, inputs, CTX, nullptr, T_, E_, T_, T_, B_ * E_, B_ * E_,
        (long)T_ * T_, (long)E_, (long)E_);

    // CP = CTX @ Wc + bc
    gemm_tc<false, true, false><<<dim3(H_ / 128, TB_ / 128, 1), 256>>>(
        CTX, nullptr, Wc, CP, bc, TB_, H_, E_, E_, H_, H_, 0, 0, 0);

    // PRE = [X | CP] @ Wall + ball
    gemm_tc<false, true, true><<<dim3(1024 / 128, TB_ / 128, 1), 256>>>(
        inputs, CP, Wall, PRE, ball, TB_, 1024, 512, E_, 1024, 1024, 0, 0, 0);

    recur7_k<<<64, 256, RSMEM>>>(PRE, out);
    (void)in_sizes; (void)n_in; (void)out_size;
}

// round 11
// speedup vs baseline: 1.0390x; 1.0390x over previous
#include <cuda_runtime.h>
#include <math.h>

#define T_  512
#define B_  64
#define E_  256
#define H_  256
#define TB_ (T_ * B_)          // 32768
#define CLU 8                  // CTAs per cluster
#define BGR 8                  // batch elements per cluster (two quads)

// ---------------- static device scratch ----------------
__device__ float g_Q  [TB_ * E_];
__device__ float g_K  [TB_ * E_];
__device__ float g_S  [B_ * T_ * T_];
__device__ float g_CTX[TB_ * E_];
__device__ float g_PRE[(long)TB_ * 4 * H_];
__device__ float g_Wall [512 * 1024];      // packed [Wf|Wi|Wu|Wo] as (512, 1024)
__device__ float g_Wfold[512 * 1024];      // rows 0..255 = Wx; rows 256..511 = Wc@Wh
__device__ float g_ball [1024];
__device__ float g_bfold[1024];            // bc@Wh + b
__device__ float g_WhC[CLU * 256 * 32 * 4];// recurrent W: [rank][k][jl][gate4]

// ---------------- bf16 2-split helpers ----------------
__device__ __forceinline__ void split_bf2(float e, float o, unsigned& hi, unsigned& lo)
{
    unsigned h;
    asm("cvt.rn.bf16x2.f32 %0, %1, %2;" : "=r"(h) : "f"(o), "f"(e));
    float eh = __uint_as_float(h << 16);
    float oh = __uint_as_float(h & 0xffff0000u);
    unsigned l;
    asm("cvt.rn.bf16x2.f32 %0, %1, %2;" : "=r"(l) : "f"(o - oh), "f"(e - eh));
    hi = h; lo = l;
}

#define MMA_BF16(c, a, b)                                                          \
    asm volatile("mma.sync.aligned.m16n8k16.row.col.f32.bf16.bf16.f32 "            \
                 "{%0,%1,%2,%3},{%4,%5,%6,%7},{%8,%9},{%0,%1,%2,%3};"              \
                 : "+f"(c[0]), "+f"(c[1]), "+f"(c[2]), "+f"(c[3])                  \
                 : "r"(a[0]), "r"(a[1]), "r"(a[2]), "r"(a[3]),                     \
                   "r"(b[0]), "r"(b[1]))

// ------ tensor-core bf16 GEMM, 128x128x16 tile, 3x split, occ 2, uint2 smem --
// hi/lo fused per element: one LDS.64 per fragment element (halves LDS count).
template<bool NT, bool BIAS, bool CONCAT>
__global__ void __launch_bounds__(256, 2) gemm_tc(
    const float* __restrict__ A, const float* __restrict__ A2,
    const float* __restrict__ B, float* __restrict__ C,
    const float* __restrict__ bias,
    int M, int N, int K, int lda, int ldb, int ldc,
    long sA, long sB, long sC)
{
    A += (long)blockIdx.z * sA;
    B += (long)blockIdx.z * sB;
    C += (long)blockIdx.z * sC;

    __shared__ uint2 As2[8][136];
    __shared__ uint2 Bs2[8][136];

    const int tid  = threadIdx.x;
    const int lane = tid & 31;
    const int warp = tid >> 5;
    const int m0 = blockIdx.y * 128;
    const int n0 = blockIdx.x * 128;
    const int wm = (warp >> 2) * 64;
    const int wn = (warp & 3) * 32;
    const int gq = lane >> 2;
    const int tg = lane & 3;

    const int ar = tid & 127;
    const int aq = (tid >> 7) * 4;
    const int bkr = tid >> 5;
    const int bn  = (tid & 31) * 4;
    const int bn_t = tid & 127;
    const int bq   = (tid >> 7) * 4;

    float acc[4][4][4];
    #pragma unroll
    for (int i = 0; i < 4; ++i)
        #pragma unroll
        for (int j = 0; j < 4; ++j)
            #pragma unroll
            for (int q = 0; q < 4; ++q) acc[i][j][q] = 0.f;

    float4 va0, va1, vb0, vb1;
    auto load_tile = [&](int k0) {
        const float* Ab = A;
        int kc = k0;
        if (CONCAT) { if (k0 >= 256) { Ab = A2; kc = k0 - 256; } }
        va0 = *(const float4*)(Ab + (long)(m0 + ar) * lda + kc + aq);
        va1 = *(const float4*)(Ab + (long)(m0 + ar) * lda + kc + aq + 8);
        if (NT) {
            vb0 = *(const float4*)(B + (long)(n0 + bn_t) * ldb + k0 + bq);
            vb1 = *(const float4*)(B + (long)(n0 + bn_t) * ldb + k0 + bq + 8);
        } else {
            vb0 = *(const float4*)(B + (long)(k0 + 2 * bkr) * ldb + n0 + bn);
            vb1 = *(const float4*)(B + (long)(k0 + 2 * bkr + 1) * ldb + n0 + bn);
        }
    };

    load_tile(0);

    for (int k0 = 0; k0 < K; k0 += 16) {
        __syncthreads();
        {
            int kp = aq >> 1;
            unsigned h, l;
            split_bf2(va0.x, va0.y, h, l); As2[kp    ][ar] = make_uint2(h, l);
            split_bf2(va0.z, va0.w, h, l); As2[kp + 1][ar] = make_uint2(h, l);
            split_bf2(va1.x, va1.y, h, l); As2[kp + 4][ar] = make_uint2(h, l);
            split_bf2(va1.z, va1.w, h, l); As2[kp + 5][ar] = make_uint2(h, l);
            if (NT) {
                int bp = bq >> 1;
                split_bf2(vb0.x, vb0.y, h, l); Bs2[bp    ][bn_t] = make_uint2(h, l);
                split_bf2(vb0.z, vb0.w, h, l); Bs2[bp + 1][bn_t] = make_uint2(h, l);
                split_bf2(vb1.x, vb1.y, h, l); Bs2[bp + 4][bn_t] = make_uint2(h, l);
                split_bf2(vb1.z, vb1.w, h, l); Bs2[bp + 5][bn_t] = make_uint2(h, l);
            } else {
                uint4 h4, l4;
                split_bf2(vb0.x, vb1.x, h4.x, l4.x);
                split_bf2(vb0.y, vb1.y, h4.y, l4.y);
                split_bf2(vb0.z, vb1.z, h4.z, l4.z);
                split_bf2(vb0.w, vb1.w, h4.w, l4.w);
                *(uint4*)&Bs2[bkr][bn]     = make_uint4(h4.x, l4.x, h4.y, l4.y);
                *(uint4*)&Bs2[bkr][bn + 2] = make_uint4(h4.z, l4.z, h4.w, l4.w);
            }
        }
        __syncthreads();

        int kn = (k0 + 16 < K) ? k0 + 16 : k0;
        load_tile(kn);

        unsigned ah[4][4], al[4][4], bh[4][2], bl[4][2];
        #pragma unroll
        for (int i = 0; i < 4; ++i) {
            int r = wm + i * 16 + gq;
            uint2 v0 = As2[tg    ][r];
            uint2 v1 = As2[tg    ][r + 8];
            uint2 v2 = As2[tg + 4][r];
            uint2 v3 = As2[tg + 4][r + 8];
            ah[i][0] = v0.x; ah[i][1] = v1.x; ah[i][2] = v2.x; ah[i][3] = v3.x;
            al[i][0] = v0.y; al[i][1] = v1.y; al[i][2] = v2.y; al[i][3] = v3.y;
        }
        #pragma unroll
        for (int j = 0; j < 4; ++j) {
            int n = wn + j * 8 + gq;
            uint2 w0 = Bs2[tg    ][n];
            uint2 w1 = Bs2[tg + 4][n];
            bh[j][0] = w0.x; bh[j][1] = w1.x;
            bl[j][0] = w0.y; bl[j][1] = w1.y;
        }
        #pragma unroll
        for (int i = 0; i < 4; ++i)
            #pragma unroll
            for (int j = 0; j < 4; ++j) {
                MMA_BF16(acc[i][j], ah[i], bh[j]);
                MMA_BF16(acc[i][j], al[i], bh[j]);
                MMA_BF16(acc[i][j], ah[i], bl[j]);
            }
    }

    #pragma unroll
    for (int i = 0; i < 4; ++i)
        #pragma unroll
        for (int j = 0; j < 4; ++j) {
            int m = m0 + wm + i * 16 + gq;
            int n = n0 + wn + j * 8 + 2 * tg;
            float2 v0 = make_float2(acc[i][j][0], acc[i][j][1]);
            float2 v1 = make_float2(acc[i][j][2], acc[i][j][3]);
            if (BIAS) {
                float b0 = bias[n], b1 = bias[n + 1];
                v0.x += b0; v0.y += b1;
                v1.x += b0; v1.y += b1;
            }
            *(float2*)(C + (long)m * ldc + n)       = v0;
            *(float2*)(C + (long)(m + 8) * ldc + n) = v1;
        }
}

// ---------------- softmax over rows of length 512 ----------
__global__ void __launch_bounds__(128) softmax_k(float* __restrict__ S)
{
    float* p = S + (long)blockIdx.x * 512;
    int tid = threadIdx.x;
    float v[4];
    float m = -1e30f;
    #pragma unroll
    for (int i = 0; i < 4; ++i) { v[i] = p[tid + 128 * i] * 0.0625f; m = fmaxf(m, v[i]); }
    __shared__ float red[128];
    red[tid] = m; __syncthreads();
    for (int s = 64; s > 0; s >>= 1) { if (tid < s) red[tid] = fmaxf(red[tid], red[tid + s]); __syncthreads(); }
    m = red[0]; __syncthreads();
    float sum = 0.f;
    #pragma unroll
    for (int i = 0; i < 4; ++i) { v[i] = __expf(v[i] - m); sum += v[i]; }
    red[tid] = sum; __syncthreads();
    for (int s = 64; s > 0; s >>= 1) { if (tid < s) red[tid] += red[tid + s]; __syncthreads(); }
    float inv = 1.f / red[0];
    #pragma unroll
    for (int i = 0; i < 4; ++i) p[tid + 128 * i] = v[i] * inv;
}

// ---------------- pack weights ----------------
__global__ void pack_init_k(const float* __restrict__ Wf, const float* __restrict__ Wi,
                            const float* __restrict__ Wu, const float* __restrict__ Wo,
                            const float* __restrict__ bf, const float* __restrict__ bi,
                            const float* __restrict__ bu, const float* __restrict__ bo)
{
    int idx = blockIdx.x * blockDim.x + threadIdx.x;
    int nt = gridDim.x * blockDim.x;
    for (int i = idx; i < CLU * 256 * 32 * 4; i += nt) {
        int r  = i >> 15;
        int k  = (i >> 7) & 255;
        int jl = (i >> 2) & 31;
        int g  = i & 3;
        const float* W = (g == 0) ? Wf : (g == 1) ? Wi : (g == 2) ? Wu : Wo;
        g_WhC[i] = W[(E_ + k) * H_ + r * 32 + jl];
    }
    for (int i = idx; i < 512 * 1024; i += nt) {
        int k = i >> 10;
        int col = i & 1023;
        int g = col >> 8, j = col & 255;
        const float* W = (g == 0) ? Wf : (g == 1) ? Wi : (g == 2) ? Wu : Wo;
        float v = W[k * 256 + j];
        g_Wall[i] = v;
        if (i < 256 * 1024) g_Wfold[i] = v;   // Wx part identical
    }
    for (int i = idx; i < 1024; i += nt) {
        int g = i >> 8;
        const float* b = (g == 0) ? bf : (g == 1) ? bi : (g == 2) ? bu : bo;
        g_ball[i] = b[i & 255];
    }
}

// bfold[col] = ball[col] + sum_h bc[h] * Wall[256+h][col]
__global__ void __launch_bounds__(256) bias_fold_k(const float* __restrict__ bc)
{
    int col = blockIdx.x * 256 + threadIdx.x;
    float s = g_ball[col];
    for (int h = 0; h < 256; ++h)
        s += bc[h] * g_Wall[(256 + h) * 1024 + col];
    g_bfold[col] = s;
}

__device__ __forceinline__ float sigf(float x)  { return 1.f / (1.f + __expf(-x)); }
__device__ __forceinline__ float tanhf_(float x){ return 2.f / (1.f + __expf(-2.f * x)) - 1.f; }

#define CARRIVE() asm volatile("barrier.cluster.arrive.aligned;" ::: "memory")
#define CWAIT()   asm volatile("barrier.cluster.wait.aligned;"   ::: "memory")

// ---------------- cluster LSTM recurrence (proven R8: one barrier per step) --
__global__ void __launch_bounds__(256, 1) __cluster_dims__(CLU, 1, 1)
recur6_k(const float* __restrict__ PRE, float* __restrict__ out)
{
    extern __shared__ float4 sm4[];
    float4* ws4  = sm4;             // [256 k][32 jl] gate4     8192 fl4
    float4* hsA  = sm4 + 8192;      // [2 buf][256 j] b4         512 fl4
    float4* hsB  = sm4 + 8704;      // [2 buf][256 j] b4         512 fl4
    float4* part = sm4 + 9216;      // 4*257 = 1028 fl4

    const int tid = threadIdx.x;
    unsigned rank;
    asm("mov.u32 %0, %%cluster_ctarank;" : "=r"(rank));
    const int bg0 = (blockIdx.x >> 3) * BGR;

    const float4* Wsrc = (const float4*)g_WhC + (long)rank * 8192;
    for (int m = tid; m < 8192; m += 256) ws4[m] = Wsrc[m];
    for (int m = tid; m < 512; m += 256) {
        hsA[m] = make_float4(0.f, 0.f, 0.f, 0.f);
        hsB[m] = make_float4(0.f, 0.f, 0.f, 0.f);
    }

    const int jl = tid & 31;
    const int ks = tid >> 5;

    const bool epi = tid < 128;
    const int  eb  = tid & 3;
    const int  ejl = tid >> 2;
    const int  jg  = rank * 32 + ejl;

    float cA = 0.f, hA = 0.f, cB = 0.f, hB = 0.f;
    float pA0 = 0.f, pA1 = 0.f, pA2 = 0.f, pA3 = 0.f;
    float pB0 = 0.f, pB1 = 0.f, pB2 = 0.f, pB3 = 0.f;
    if (epi) {
        const float* pp = PRE + ((long)0 * B_ + bg0 + eb) * 1024 + jg;
        pA0 = pp[0]; pA1 = pp[256]; pA2 = pp[512]; pA3 = pp[768];
        const float* qq = PRE + ((long)0 * B_ + bg0 + 4 + eb) * 1024 + jg;
        pB0 = qq[0]; pB1 = qq[256]; pB2 = qq[512]; pB3 = qq[768];
    }

    const unsigned hsA_u32 = (unsigned)__cvta_generic_to_shared(hsA);
    const unsigned hsB_u32 = (unsigned)__cvta_generic_to_shared(hsB);

    __syncthreads();
    CARRIVE(); CWAIT();

    for (int t = 0; t < T_; ++t) {
        const int buf = t & 1;

        // ---------- quad A compute ----------
        {
            const float4* hp = hsA + buf * 256 + ks * 32;
            const float4* wp = ws4 + (ks * 32) * 32 + jl;
            float4 a0 = {0,0,0,0}, a1 = {0,0,0,0}, a2 = {0,0,0,0}, a3 = {0,0,0,0};
            #pragma unroll 8
            for (int u = 0; u < 32; ++u) {
                float4 hv = hp[u];
                float4 wv = wp[u * 32];
                a0.x += hv.x*wv.x; a0.y += hv.x*wv.y; a0.z += hv.x*wv.z; a0.w += hv.x*wv.w;
                a1.x += hv.y*wv.x; a1.y += hv.y*wv.y; a1.z += hv.y*wv.z; a1.w += hv.y*wv.w;
                a2.x += hv.z*wv.x; a2.y += hv.z*wv.y; a2.z += hv.z*wv.z; a2.w += hv.z*wv.w;
                a3.x += hv.w*wv.x; a3.y += hv.w*wv.y; a3.z += hv.w*wv.z; a3.w += hv.w*wv.w;
            }
            part[0 * 257 + ks * 32 + jl] = a0;
            part[1 * 257 + ks * 32 + jl] = a1;
            part[2 * 257 + ks * 32 + jl] = a2;
            part[3 * 257 + ks * 32 + jl] = a3;
        }
        __syncthreads();
        if (epi) {
            float4 s = part[eb * 257 + 0 * 32 + ejl];
            #pragma unroll
            for (int q = 1; q < 8; ++q) {
                float4 p = part[eb * 257 + q * 32 + ejl];
                s.x += p.x; s.y += p.y; s.z += p.z; s.w += p.w;
            }
            float fg = sigf  (s.x + pA0);
            float ig = sigf  (s.y + pA1);
            float ug = tanhf_(s.z + pA2);
            float og = sigf  (s.w + pA3);
            cA = fg * cA + ig * ug;
            hA = og * tanhf_(cA);
            out[((long)t * B_ + bg0 + eb) * H_ + jg] = hA;
            unsigned laddr = hsA_u32 + ((((buf ^ 1) * 256 + jg) * 4 + eb) << 2);
            #pragma unroll
            for (int r2 = 0; r2 < CLU; ++r2) {
                unsigned ra;
                asm volatile("mapa.shared::cluster.u32 %0, %1, %2;"
                             : "=r"(ra) : "r"(laddr), "r"(r2));
                asm volatile("st.shared::cluster.f32 [%0], %1;"
                             :: "r"(ra), "f"(hA) : "memory");
            }
            int tn = (t < T_ - 1) ? t + 1 : t;
            const float* pp = PRE + ((long)tn * B_ + bg0 + eb) * 1024 + jg;
            pA0 = pp[0]; pA1 = pp[256]; pA2 = pp[512]; pA3 = pp[768];
        }
        __syncthreads();

        // ---------- quad B compute ----------
        {
            const float4* hp = hsB + buf * 256 + ks * 32;
            const float4* wp = ws4 + (ks * 32) * 32 + jl;
            float4 a0 = {0,0,0,0}, a1 = {0,0,0,0}, a2 = {0,0,0,0}, a3 = {0,0,0,0};
            #pragma unroll 8
            for (int u = 0; u < 32; ++u) {
                float4 hv = hp[u];
                float4 wv = wp[u * 32];
                a0.x += hv.x*wv.x; a0.y += hv.x*wv.y; a0.z += hv.x*wv.z; a0.w += hv.x*wv.w;
                a1.x += hv.y*wv.x; a1.y += hv.y*wv.y; a1.z += hv.y*wv.z; a1.w += hv.y*wv.w;
                a2.x += hv.z*wv.x; a2.y += hv.z*wv.y; a2.z += hv.z*wv.z; a2.w += hv.z*wv.w;
                a3.x += hv.w*wv.x; a3.y += hv.w*wv.y; a3.z += hv.w*wv.z; a3.w += hv.w*wv.w;
            }
            part[0 * 257 + ks * 32 + jl] = a0;
            part[1 * 257 + ks * 32 + jl] = a1;
            part[2 * 257 + ks * 32 + jl] = a2;
            part[3 * 257 + ks * 32 + jl] = a3;
        }
        __syncthreads();
        if (epi) {
            float4 s = part[eb * 257 + 0 * 32 + ejl];
            #pragma unroll
            for (int q = 1; q < 8; ++q) {
                float4 p = part[eb * 257 + q * 32 + ejl];
                s.x += p.x; s.y += p.y; s.z += p.z; s.w += p.w;
            }
            float fg = sigf  (s.x + pB0);
            float ig = sigf  (s.y + pB1);
            float ug = tanhf_(s.z + pB2);
            float og = sigf  (s.w + pB3);
            cB = fg * cB + ig * ug;
            hB = og * tanhf_(cB);
            out[((long)t * B_ + bg0 + 4 + eb) * H_ + jg] = hB;
            unsigned laddr = hsB_u32 + ((((buf ^ 1) * 256 + jg) * 4 + eb) << 2);
            #pragma unroll
            for (int r2 = 0; r2 < CLU; ++r2) {
                unsigned ra;
                asm volatile("mapa.shared::cluster.u32 %0, %1, %2;"
                             : "=r"(ra) : "r"(laddr), "r"(r2));
                asm volatile("st.shared::cluster.f32 [%0], %1;"
                             :: "r"(ra), "f"(hB) : "memory");
            }
            int tn = (t < T_ - 1) ? t + 1 : t;
            const float* qq = PRE + ((long)tn * B_ + bg0 + 4 + eb) * 1024 + jg;
            pB0 = qq[0]; pB1 = qq[256]; pB2 = qq[512]; pB3 = qq[768];
        }

        CARRIVE();
        CWAIT();
    }

    if (epi) {
        out[(long)TB_ * H_ + (bg0 + eb) * H_ + jg] = hA;
        out[(long)TB_ * H_ + (bg0 + 4 + eb) * H_ + jg] = hB;
        out[(long)TB_ * H_ + (long)B_ * H_ + (bg0 + eb) * H_ + jg] = cA;
        out[(long)TB_ * H_ + (long)B_ * H_ + (bg0 + 4 + eb) * H_ + jg] = cB;
    }
}

// ---------------- launch ----------------
extern "C" void kernel_launch(void* const* d_in, const int* in_sizes, int n_in,
                              void* d_out, int out_size)
{
    const float* inputs = (const float*)d_in[0];
    const float* rot    = (const float*)d_in[1];
    const float* ent    = (const float*)d_in[2];
    const float* Wf = (const float*)d_in[3];  const float* bf = (const float*)d_in[4];
    const float* Wi = (const float*)d_in[5];  const float* bi = (const float*)d_in[6];
    const float* Wu = (const float*)d_in[7];  const float* bu = (const float*)d_in[8];
    const float* Wo = (const float*)d_in[9];  const float* bo = (const float*)d_in[10];
    const float* Wc = (const float*)d_in[11]; const float* bc = (const float*)d_in[12];
    float* out = (float*)d_out;

    float *Q, *K, *S, *CTX, *PRE, *Wall, *Wfold, *bfold;
    cudaGetSymbolAddress((void**)&Q,     g_Q);
    cudaGetSymbolAddress((void**)&K,     g_K);
    cudaGetSymbolAddress((void**)&S,     g_S);
    cudaGetSymbolAddress((void**)&CTX,   g_CTX);
    cudaGetSymbolAddress((void**)&PRE,   g_PRE);
    cudaGetSymbolAddress((void**)&Wall,  g_Wall);
    cudaGetSymbolAddress((void**)&Wfold, g_Wfold);
    cudaGetSymbolAddress((void**)&bfold, g_bfold);

    const int RSMEM = (8192 + 512 + 512 + 1028) * 16;
    cudaFuncSetAttribute(recur6_k, cudaFuncAttributeMaxDynamicSharedMemorySize, RSMEM);

    pack_init_k<<<256, 256>>>(Wf, Wi, Wu, Wo, bf, bi, bu, bo);
    bias_fold_k<<<4, 256>>>(bc);

    // Wfold[256:512] = Wc @ Wall[256:512]   (M=256, N=1024, K=256)
    gemm_tc<false, false, false><<<dim3(1024 / 128, 256 / 128, 1), 256>>>(
        Wc, nullptr, Wall + 256 * 1024, Wfold + 256 * 1024, nullptr,
        256, 1024, 256, 256, 1024, 1024, 0, 0, 0);

    // Q = X @ rot ; K = X @ ent
    gemm_tc<false, false, false><<<dim3(E_ / 128, TB_ / 128, 1), 256>>>(
        inputs, nullptr, rot, Q, nullptr, TB_, E_, E_, E_, E_, E_, 0, 0, 0);
    gemm_tc<false, false, false><<<dim3(E_ / 128, TB_ / 128, 1), 256>>>(
        inputs, nullptr, ent, K, nullptr, TB_, E_, E_, E_, E_, E_, 0, 0, 0);

    // scores_b = Q_b @ K_b^T
    gemm_tc<true, false, false><<<dim3(T_ / 128, T_ / 128, B_), 256>>>(
        Q, nullptr, K, S, nullptr, T_, T_, E_, B_ * E_, B_ * E_, T_,
        (long)E_, (long)E_, (long)T_ * T_);

    softmax_k<<<B_ * T_, 128>>>(S);

    // context_b = S_b @ X_b
    gemm_tc<false, false, false><<<dim3(E_ / 128, T_ / 128, B_), 256>>>(
        S, nullptr, inputs, CTX, nullptr, T_, E_, T_, T_, B_ * E_, B_ * E_,
        (long)T_ * T_, (long)E_, (long)E_);

    // PRE = [X | CTX] @ Wfold + bfold   (CP GEMM folded away)
    gemm_tc<false, true, true><<<dim3(1024 / 128, TB_ / 128, 1), 256>>>(
        inputs, CTX, Wfold, PRE, bfold, TB_, 1024, 512, E_, 1024, 1024, 0, 0, 0);

    recur6_k<<<64, 256, RSMEM>>>(PRE, out);
    (void)in_sizes; (void)n_in; (void)out_size;
}

// round 12
// speedup vs baseline: 1.0926x; 1.0516x over previous
#include <cuda_runtime.h>
#include <math.h>

#define T_  512
#define B_  64
#define E_  256
#define H_  256
#define TB_ (T_ * B_)          // 32768
#define CLU 8                  // CTAs per cluster
#define BGR 8                  // batch elements per cluster (two quads)

// ---------------- static device scratch ----------------
__device__ float g_Q  [TB_ * E_];
__device__ float g_K  [TB_ * E_];
__device__ float g_S  [B_ * T_ * T_];
__device__ float g_CTX[TB_ * E_];
__device__ float g_PRE[(long)TB_ * 4 * H_];
__device__ float g_Wall [512 * 1024];      // packed [Wf|Wi|Wu|Wo] as (512, 1024)
__device__ float g_Wfold[512 * 1024];      // rows 0..255 = Wx; rows 256..511 = Wc@Wh
__device__ float g_ball [1024];
__device__ float g_bfold[1024];            // bc@Wh + b
__device__ float g_WhC[CLU * 256 * 32 * 4];// recurrent W: [rank][k][jl][gate4]

// ---------------- bf16 2-split helpers ----------------
__device__ __forceinline__ void split_bf2(float e, float o, unsigned& hi, unsigned& lo)
{
    unsigned h;
    asm("cvt.rn.bf16x2.f32 %0, %1, %2;" : "=r"(h) : "f"(o), "f"(e));
    float eh = __uint_as_float(h << 16);
    float oh = __uint_as_float(h & 0xffff0000u);
    unsigned l;
    asm("cvt.rn.bf16x2.f32 %0, %1, %2;" : "=r"(l) : "f"(o - oh), "f"(e - eh));
    hi = h; lo = l;
}

#define MMA_BF16(c, a, b)                                                          \
    asm volatile("mma.sync.aligned.m16n8k16.row.col.f32.bf16.bf16.f32 "            \
                 "{%0,%1,%2,%3},{%4,%5,%6,%7},{%8,%9},{%0,%1,%2,%3};"              \
                 : "+f"(c[0]), "+f"(c[1]), "+f"(c[2]), "+f"(c[3])                  \
                 : "r"(a[0]), "r"(a[1]), "r"(a[2]), "r"(a[3]),                     \
                   "r"(b[0]), "r"(b[1]))

// ---------------- tensor-core bf16 GEMM, 128x128x16 tile, 3x split, occ 2 ----
// (exact proven R8 version: single smem buffer, separate hi/lo, reg prefetch)
template<bool NT, bool BIAS, bool CONCAT>
__global__ void __launch_bounds__(256, 2) gemm_tc(
    const float* __restrict__ A, const float* __restrict__ A2,
    const float* __restrict__ B, float* __restrict__ C,
    const float* __restrict__ bias,
    int M, int N, int K, int lda, int ldb, int ldc,
    long sA, long sB, long sC)
{
    A += (long)blockIdx.z * sA;
    B += (long)blockIdx.z * sB;
    C += (long)blockIdx.z * sC;

    __shared__ unsigned As_hi[8][136], As_lo[8][136];
    __shared__ unsigned Bs_hi[8][136], Bs_lo[8][136];

    const int tid  = threadIdx.x;
    const int lane = tid & 31;
    const int warp = tid >> 5;
    const int m0 = blockIdx.y * 128;
    const int n0 = blockIdx.x * 128;
    const int wm = (warp >> 2) * 64;
    const int wn = (warp & 3) * 32;
    const int gq = lane >> 2;
    const int tg = lane & 3;

    const int ar = tid & 127;
    const int aq = (tid >> 7) * 4;
    const int bkr = tid >> 5;
    const int bn  = (tid & 31) * 4;
    const int bn_t = tid & 127;
    const int bq   = (tid >> 7) * 4;

    float acc[4][4][4];
    #pragma unroll
    for (int i = 0; i < 4; ++i)
        #pragma unroll
        for (int j = 0; j < 4; ++j)
            #pragma unroll
            for (int q = 0; q < 4; ++q) acc[i][j][q] = 0.f;

    float4 va0, va1, vb0, vb1;
    auto load_tile = [&](int k0) {
        const float* Ab = A;
        int kc = k0;
        if (CONCAT) { if (k0 >= 256) { Ab = A2; kc = k0 - 256; } }
        va0 = *(const float4*)(Ab + (long)(m0 + ar) * lda + kc + aq);
        va1 = *(const float4*)(Ab + (long)(m0 + ar) * lda + kc + aq + 8);
        if (NT) {
            vb0 = *(const float4*)(B + (long)(n0 + bn_t) * ldb + k0 + bq);
            vb1 = *(const float4*)(B + (long)(n0 + bn_t) * ldb + k0 + bq + 8);
        } else {
            vb0 = *(const float4*)(B + (long)(k0 + 2 * bkr) * ldb + n0 + bn);
            vb1 = *(const float4*)(B + (long)(k0 + 2 * bkr + 1) * ldb + n0 + bn);
        }
    };

    load_tile(0);

    for (int k0 = 0; k0 < K; k0 += 16) {
        __syncthreads();
        {
            int kp = aq >> 1;
            split_bf2(va0.x, va0.y, As_hi[kp    ][ar], As_lo[kp    ][ar]);
            split_bf2(va0.z, va0.w, As_hi[kp + 1][ar], As_lo[kp + 1][ar]);
            split_bf2(va1.x, va1.y, As_hi[kp + 4][ar], As_lo[kp + 4][ar]);
            split_bf2(va1.z, va1.w, As_hi[kp + 5][ar], As_lo[kp + 5][ar]);
            if (NT) {
                int bp = bq >> 1;
                split_bf2(vb0.x, vb0.y, Bs_hi[bp    ][bn_t], Bs_lo[bp    ][bn_t]);
                split_bf2(vb0.z, vb0.w, Bs_hi[bp + 1][bn_t], Bs_lo[bp + 1][bn_t]);
                split_bf2(vb1.x, vb1.y, Bs_hi[bp + 4][bn_t], Bs_lo[bp + 4][bn_t]);
                split_bf2(vb1.z, vb1.w, Bs_hi[bp + 5][bn_t], Bs_lo[bp + 5][bn_t]);
            } else {
                uint4 h4, l4;
                split_bf2(vb0.x, vb1.x, h4.x, l4.x);
                split_bf2(vb0.y, vb1.y, h4.y, l4.y);
                split_bf2(vb0.z, vb1.z, h4.z, l4.z);
                split_bf2(vb0.w, vb1.w, h4.w, l4.w);
                *(uint4*)&Bs_hi[bkr][bn] = h4;
                *(uint4*)&Bs_lo[bkr][bn] = l4;
            }
        }
        __syncthreads();

        int kn = (k0 + 16 < K) ? k0 + 16 : k0;
        load_tile(kn);

        unsigned ah[4][4], al[4][4], bh[4][2], bl[4][2];
        #pragma unroll
        for (int i = 0; i < 4; ++i) {
            int r = wm + i * 16 + gq;
            ah[i][0] = As_hi[tg    ][r];
            ah[i][1] = As_hi[tg    ][r + 8];
            ah[i][2] = As_hi[tg + 4][r];
            ah[i][3] = As_hi[tg + 4][r + 8];
            al[i][0] = As_lo[tg    ][r];
            al[i][1] = As_lo[tg    ][r + 8];
            al[i][2] = As_lo[tg + 4][r];
            al[i][3] = As_lo[tg + 4][r + 8];
        }
        #pragma unroll
        for (int j = 0; j < 4; ++j) {
            int n = wn + j * 8 + gq;
            bh[j][0] = Bs_hi[tg    ][n];
            bh[j][1] = Bs_hi[tg + 4][n];
            bl[j][0] = Bs_lo[tg    ][n];
            bl[j][1] = Bs_lo[tg + 4][n];
        }
        #pragma unroll
        for (int i = 0; i < 4; ++i)
            #pragma unroll
            for (int j = 0; j < 4; ++j) {
                MMA_BF16(acc[i][j], ah[i], bh[j]);
                MMA_BF16(acc[i][j], al[i], bh[j]);
                MMA_BF16(acc[i][j], ah[i], bl[j]);
            }
    }

    #pragma unroll
    for (int i = 0; i < 4; ++i)
        #pragma unroll
        for (int j = 0; j < 4; ++j) {
            int m = m0 + wm + i * 16 + gq;
            int n = n0 + wn + j * 8 + 2 * tg;
            float2 v0 = make_float2(acc[i][j][0], acc[i][j][1]);
            float2 v1 = make_float2(acc[i][j][2], acc[i][j][3]);
            if (BIAS) {
                float b0 = bias[n], b1 = bias[n + 1];
                v0.x += b0; v0.y += b1;
                v1.x += b0; v1.y += b1;
            }
            *(float2*)(C + (long)m * ldc + n)       = v0;
            *(float2*)(C + (long)(m + 8) * ldc + n) = v1;
        }
}

// ---------------- softmax over rows of length 512 ----------
__global__ void __launch_bounds__(128) softmax_k(float* __restrict__ S)
{
    float* p = S + (long)blockIdx.x * 512;
    int tid = threadIdx.x;
    float v[4];
    float m = -1e30f;
    #pragma unroll
    for (int i = 0; i < 4; ++i) { v[i] = p[tid + 128 * i] * 0.0625f; m = fmaxf(m, v[i]); }
    __shared__ float red[128];
    red[tid] = m; __syncthreads();
    for (int s = 64; s > 0; s >>= 1) { if (tid < s) red[tid] = fmaxf(red[tid], red[tid + s]); __syncthreads(); }
    m = red[0]; __syncthreads();
    float sum = 0.f;
    #pragma unroll
    for (int i = 0; i < 4; ++i) { v[i] = __expf(v[i] - m); sum += v[i]; }
    red[tid] = sum; __syncthreads();
    for (int s = 64; s > 0; s >>= 1) { if (tid < s) red[tid] += red[tid + s]; __syncthreads(); }
    float inv = 1.f / red[0];
    #pragma unroll
    for (int i = 0; i < 4; ++i) p[tid + 128 * i] = v[i] * inv;
}

// ---------------- pack weights ----------------
__global__ void pack_init_k(const float* __restrict__ Wf, const float* __restrict__ Wi,
                            const float* __restrict__ Wu, const float* __restrict__ Wo,
                            const float* __restrict__ bf, const float* __restrict__ bi,
                            const float* __restrict__ bu, const float* __restrict__ bo)
{
    int idx = blockIdx.x * blockDim.x + threadIdx.x;
    int nt = gridDim.x * blockDim.x;
    for (int i = idx; i < CLU * 256 * 32 * 4; i += nt) {
        int r  = i >> 15;
        int k  = (i >> 7) & 255;
        int jl = (i >> 2) & 31;
        int g  = i & 3;
        const float* W = (g == 0) ? Wf : (g == 1) ? Wi : (g == 2) ? Wu : Wo;
        g_WhC[i] = W[(E_ + k) * H_ + r * 32 + jl];
    }
    for (int i = idx; i < 512 * 1024; i += nt) {
        int k = i >> 10;
        int col = i & 1023;
        int g = col >> 8, j = col & 255;
        const float* W = (g == 0) ? Wf : (g == 1) ? Wi : (g == 2) ? Wu : Wo;
        float v = W[k * 256 + j];
        g_Wall[i] = v;
        if (i < 256 * 1024) g_Wfold[i] = v;   // Wx part identical
    }
    for (int i = idx; i < 1024; i += nt) {
        int g = i >> 8;
        const float* b = (g == 0) ? bf : (g == 1) ? bi : (g == 2) ? bu : bo;
        g_ball[i] = b[i & 255];
    }
}

// bfold[col] = ball[col] + sum_h bc[h] * Wall[256+h][col]
// warp-parallel: one warp per column, lanes split h, shfl reduce.
__global__ void __launch_bounds__(256) bias_fold_k(const float* __restrict__ bc)
{
    int col  = blockIdx.x * 8 + (threadIdx.x >> 5);
    int lane = threadIdx.x & 31;
    float s = 0.f;
    #pragma unroll
    for (int h = lane; h < 256; h += 32)
        s += bc[h] * g_Wall[(256 + h) * 1024 + col];
    #pragma unroll
    for (int o = 16; o > 0; o >>= 1)
        s += __shfl_xor_sync(0xffffffffu, s, o);
    if (lane == 0) g_bfold[col] = g_ball[col] + s;
}

__device__ __forceinline__ float sigf(float x)  { return 1.f / (1.f + __expf(-x)); }
__device__ __forceinline__ float tanhf_(float x){ return 2.f / (1.f + __expf(-2.f * x)) - 1.f; }

#define CARRIVE() asm volatile("barrier.cluster.arrive.aligned;" ::: "memory")
#define CWAIT()   asm volatile("barrier.cluster.wait.aligned;"   ::: "memory")

// ---------------- cluster LSTM recurrence (proven R8: one barrier per step) --
__global__ void __launch_bounds__(256, 1) __cluster_dims__(CLU, 1, 1)
recur6_k(const float* __restrict__ PRE, float* __restrict__ out)
{
    extern __shared__ float4 sm4[];
    float4* ws4  = sm4;             // [256 k][32 jl] gate4     8192 fl4
    float4* hsA  = sm4 + 8192;      // [2 buf][256 j] b4         512 fl4
    float4* hsB  = sm4 + 8704;      // [2 buf][256 j] b4         512 fl4
    float4* part = sm4 + 9216;      // 4*257 = 1028 fl4

    const int tid = threadIdx.x;
    unsigned rank;
    asm("mov.u32 %0, %%cluster_ctarank;" : "=r"(rank));
    const int bg0 = (blockIdx.x >> 3) * BGR;

    const float4* Wsrc = (const float4*)g_WhC + (long)rank * 8192;
    for (int m = tid; m < 8192; m += 256) ws4[m] = Wsrc[m];
    for (int m = tid; m < 512; m += 256) {
        hsA[m] = make_float4(0.f, 0.f, 0.f, 0.f);
        hsB[m] = make_float4(0.f, 0.f, 0.f, 0.f);
    }

    const int jl = tid & 31;
    const int ks = tid >> 5;

    const bool epi = tid < 128;
    const int  eb  = tid & 3;
    const int  ejl = tid >> 2;
    const int  jg  = rank * 32 + ejl;

    float cA = 0.f, hA = 0.f, cB = 0.f, hB = 0.f;
    float pA0 = 0.f, pA1 = 0.f, pA2 = 0.f, pA3 = 0.f;
    float pB0 = 0.f, pB1 = 0.f, pB2 = 0.f, pB3 = 0.f;
    if (epi) {
        const float* pp = PRE + ((long)0 * B_ + bg0 + eb) * 1024 + jg;
        pA0 = pp[0]; pA1 = pp[256]; pA2 = pp[512]; pA3 = pp[768];
        const float* qq = PRE + ((long)0 * B_ + bg0 + 4 + eb) * 1024 + jg;
        pB0 = qq[0]; pB1 = qq[256]; pB2 = qq[512]; pB3 = qq[768];
    }

    const unsigned hsA_u32 = (unsigned)__cvta_generic_to_shared(hsA);
    const unsigned hsB_u32 = (unsigned)__cvta_generic_to_shared(hsB);

    __syncthreads();
    CARRIVE(); CWAIT();

    for (int t = 0; t < T_; ++t) {
        const int buf = t & 1;

        // ---------- quad A compute ----------
        {
            const float4* hp = hsA + buf * 256 + ks * 32;
            const float4* wp = ws4 + (ks * 32) * 32 + jl;
            float4 a0 = {0,0,0,0}, a1 = {0,0,0,0}, a2 = {0,0,0,0}, a3 = {0,0,0,0};
            #pragma unroll 8
            for (int u = 0; u < 32; ++u) {
                float4 hv = hp[u];
                float4 wv = wp[u * 32];
                a0.x += hv.x*wv.x; a0.y += hv.x*wv.y; a0.z += hv.x*wv.z; a0.w += hv.x*wv.w;
                a1.x += hv.y*wv.x; a1.y += hv.y*wv.y; a1.z += hv.y*wv.z; a1.w += hv.y*wv.w;
                a2.x += hv.z*wv.x; a2.y += hv.z*wv.y; a2.z += hv.z*wv.z; a2.w += hv.z*wv.w;
                a3.x += hv.w*wv.x; a3.y += hv.w*wv.y; a3.z += hv.w*wv.z; a3.w += hv.w*wv.w;
            }
            part[0 * 257 + ks * 32 + jl] = a0;
            part[1 * 257 + ks * 32 + jl] = a1;
            part[2 * 257 + ks * 32 + jl] = a2;
            part[3 * 257 + ks * 32 + jl] = a3;
        }
        __syncthreads();
        if (epi) {
            float4 s = part[eb * 257 + 0 * 32 + ejl];
            #pragma unroll
            for (int q = 1; q < 8; ++q) {
                float4 p = part[eb * 257 + q * 32 + ejl];
                s.x += p.x; s.y += p.y; s.z += p.z; s.w += p.w;
            }
            float fg = sigf  (s.x + pA0);
            float ig = sigf  (s.y + pA1);
            float ug = tanhf_(s.z + pA2);
            float og = sigf  (s.w + pA3);
            cA = fg * cA + ig * ug;
            hA = og * tanhf_(cA);
            out[((long)t * B_ + bg0 + eb) * H_ + jg] = hA;
            unsigned laddr = hsA_u32 + ((((buf ^ 1) * 256 + jg) * 4 + eb) << 2);
            #pragma unroll
            for (int r2 = 0; r2 < CLU; ++r2) {
                unsigned ra;
                asm volatile("mapa.shared::cluster.u32 %0, %1, %2;"
                             : "=r"(ra) : "r"(laddr), "r"(r2));
                asm volatile("st.shared::cluster.f32 [%0], %1;"
                             :: "r"(ra), "f"(hA) : "memory");
            }
            int tn = (t < T_ - 1) ? t + 1 : t;
            const float* pp = PRE + ((long)tn * B_ + bg0 + eb) * 1024 + jg;
            pA0 = pp[0]; pA1 = pp[256]; pA2 = pp[512]; pA3 = pp[768];
        }
        __syncthreads();

        // ---------- quad B compute ----------
        {
            const float4* hp = hsB + buf * 256 + ks * 32;
            const float4* wp = ws4 + (ks * 32) * 32 + jl;
            float4 a0 = {0,0,0,0}, a1 = {0,0,0,0}, a2 = {0,0,0,0}, a3 = {0,0,0,0};
            #pragma unroll 8
            for (int u = 0; u < 32; ++u) {
                float4 hv = hp[u];
                float4 wv = wp[u * 32];
                a0.x += hv.x*wv.x; a0.y += hv.x*wv.y; a0.z += hv.x*wv.z; a0.w += hv.x*wv.w;
                a1.x += hv.y*wv.x; a1.y += hv.y*wv.y; a1.z += hv.y*wv.z; a1.w += hv.y*wv.w;
                a2.x += hv.z*wv.x; a2.y += hv.z*wv.y; a2.z += hv.z*wv.z; a2.w += hv.z*wv.w;
                a3.x += hv.w*wv.x; a3.y += hv.w*wv.y; a3.z += hv.w*wv.z; a3.w += hv.w*wv.w;
            }
            part[0 * 257 + ks * 32 + jl] = a0;
            part[1 * 257 + ks * 32 + jl] = a1;
            part[2 * 257 + ks * 32 + jl] = a2;
            part[3 * 257 + ks * 32 + jl] = a3;
        }
        __syncthreads();
        if (epi) {
            float4 s = part[eb * 257 + 0 * 32 + ejl];
            #pragma unroll
            for (int q = 1; q < 8; ++q) {
                float4 p = part[eb * 257 + q * 32 + ejl];
                s.x += p.x; s.y += p.y; s.z += p.z; s.w += p.w;
            }
            float fg = sigf  (s.x + pB0);
            float ig = sigf  (s.y + pB1);
            float ug = tanhf_(s.z + pB2);
            float og = sigf  (s.w + pB3);
            cB = fg * cB + ig * ug;
            hB = og * tanhf_(cB);
            out[((long)t * B_ + bg0 + 4 + eb) * H_ + jg] = hB;
            unsigned laddr = hsB_u32 + ((((buf ^ 1) * 256 + jg) * 4 + eb) << 2);
            #pragma unroll
            for (int r2 = 0; r2 < CLU; ++r2) {
                unsigned ra;
                asm volatile("mapa.shared::cluster.u32 %0, %1, %2;"
                             : "=r"(ra) : "r"(laddr), "r"(r2));
                asm volatile("st.shared::cluster.f32 [%0], %1;"
                             :: "r"(ra), "f"(hB) : "memory");
            }
            int tn = (t < T_ - 1) ? t + 1 : t;
            const float* qq = PRE + ((long)tn * B_ + bg0 + 4 + eb) * 1024 + jg;
            pB0 = qq[0]; pB1 = qq[256]; pB2 = qq[512]; pB3 = qq[768];
        }

        CARRIVE();
        CWAIT();
    }

    if (epi) {
        out[(long)TB_ * H_ + (bg0 + eb) * H_ + jg] = hA;
        out[(long)TB_ * H_ + (bg0 + 4 + eb) * H_ + jg] = hB;
        out[(long)TB_ * H_ + (long)B_ * H_ + (bg0 + eb) * H_ + jg] = cA;
        out[(long)TB_ * H_ + (long)B_ * H_ + (bg0 + 4 + eb) * H_ + jg] = cB;
    }
}

// ---------------- launch ----------------
extern "C" void kernel_launch(void* const* d_in, const int* in_sizes, int n_in,
                              void* d_out, int out_size)
{
    const float* inputs = (const float*)d_in[0];
    const float* rot    = (const float*)d_in[1];
    const float* ent    = (const float*)d_in[2];
    const float* Wf = (const float*)d_in[3];  const float* bf = (const float*)d_in[4];
    const float* Wi = (const float*)d_in[5];  const float* bi = (const float*)d_in[6];
    const float* Wu = (const float*)d_in[7];  const float* bu = (const float*)d_in[8];
    const float* Wo = (const float*)d_in[9];  const float* bo = (const float*)d_in[10];
    const float* Wc = (const float*)d_in[11]; const float* bc = (const float*)d_in[12];
    float* out = (float*)d_out;

    float *Q, *K, *S, *CTX, *PRE, *Wall, *Wfold, *bfold;
    cudaGetSymbolAddress((void**)&Q,     g_Q);
    cudaGetSymbolAddress((void**)&K,     g_K);
    cudaGetSymbolAddress((void**)&S,     g_S);
    cudaGetSymbolAddress((void**)&CTX,   g_CTX);
    cudaGetSymbolAddress((void**)&PRE,   g_PRE);
    cudaGetSymbolAddress((void**)&Wall,  g_Wall);
    cudaGetSymbolAddress((void**)&Wfold, g_Wfold);
    cudaGetSymbolAddress((void**)&bfold, g_bfold);

    const int RSMEM = (8192 + 512 + 512 + 1028) * 16;
    cudaFuncSetAttribute(recur6_k, cudaFuncAttributeMaxDynamicSharedMemorySize, RSMEM);

    pack_init_k<<<256, 256>>>(Wf, Wi, Wu, Wo, bf, bi, bu, bo);
    bias_fold_k<<<128, 256>>>(bc);

    // Wfold[256:512] = Wc @ Wall[256:512]   (M=256, N=1024, K=256)
    gemm_tc<false, false, false><<<dim3(1024 / 128, 256 / 128, 1), 256>>>(
        Wc, nullptr, Wall + 256 * 1024, Wfold + 256 * 1024, nullptr,
        256, 1024, 256, 256, 1024, 1024, 0, 0, 0);

    // Q = X @ rot ; K = X @ ent
    gemm_tc<false, false, false><<<dim3(E_ / 128, TB_ / 128, 1), 256>>>(
        inputs, nullptr, rot, Q, nullptr, TB_, E_, E_, E_, E_, E_, 0, 0, 0);
    gemm_tc<false, false, false><<<dim3(E_ / 128, TB_ / 128, 1), 256>>>(
        inputs, nullptr, ent, K, nullptr, TB_, E_, E_, E_, E_, E_, 0, 0, 0);

    // scores_b = Q_b @ K_b^T
    gemm_tc<true, false, false><<<dim3(T_ / 128, T_ / 128, B_), 256>>>(
        Q, nullptr, K, S, nullptr, T_, T_, E_, B_ * E_, B_ * E_, T_,
        (long)E_, (long)E_, (long)T_ * T_);

    softmax_k<<<B_ * T_, 128>>>(S);

    // context_b = S_b @ X_b
    gemm_tc<false, false, false><<<dim3(E_ / 128, T_ / 128, B_), 256>>>(
        S, nullptr, inputs, CTX, nullptr, T_, E_, T_, T_, B_ * E_, B_ * E_,
        (long)T_ * T_, (long)E_, (long)E_);

    // PRE = [X | CTX] @ Wfold + bfold   (CP GEMM folded away)
    gemm_tc<false, true, true><<<dim3(1024 / 128, TB_ / 128, 1), 256>>>(
        inputs, CTX, Wfold, PRE, bfold, TB_, 1024, 512, E_, 1024, 1024, 0, 0, 0);

    recur6_k<<<64, 256, RSMEM>>>(PRE, out);
    (void)in_sizes; (void)n_in; (void)out_size;
}

// round 13
// speedup vs baseline: 1.5033x; 1.3758x over previous
#include <cuda_runtime.h>
#include <math.h>

#define T_  512
#define B_  64
#define E_  256
#define H_  256
#define TB_ (T_ * B_)          // 32768
#define CLU 8                  // CTAs per cluster
#define BGR 8                  // batch elements per cluster

// ---------------- static device scratch ----------------
__device__ float g_Q  [TB_ * E_];
__device__ float g_K  [TB_ * E_];
__device__ float g_S  [B_ * T_ * T_];
__device__ float g_CTX[TB_ * E_];
__device__ float g_PRE[(long)TB_ * 4 * H_];
__device__ float g_Wall [512 * 1024];      // packed [Wf|Wi|Wu|Wo] as (512, 1024)
__device__ float g_Wfold[512 * 1024];      // rows 0..255 = Wx; rows 256..511 = Wc@Wh
__device__ float g_ball [1024];
__device__ float g_bfold[1024];            // bc@Wh + b
// recurrent W for MMA: bf16 split pairs along k, [rank][row c(128)][kp(140 pad)]
__device__ unsigned g_WAh[CLU * 128 * 140];
__device__ unsigned g_WAl[CLU * 128 * 140];

// ---------------- bf16 2-split helpers ----------------
__device__ __forceinline__ void split_bf2(float e, float o, unsigned& hi, unsigned& lo)
{
    unsigned h;
    asm("cvt.rn.bf16x2.f32 %0, %1, %2;" : "=r"(h) : "f"(o), "f"(e));
    float eh = __uint_as_float(h << 16);
    float oh = __uint_as_float(h & 0xffff0000u);
    unsigned l;
    asm("cvt.rn.bf16x2.f32 %0, %1, %2;" : "=r"(l) : "f"(o - oh), "f"(e - eh));
    hi = h; lo = l;
}

#define MMA_BF16(c, a, b)                                                          \
    asm volatile("mma.sync.aligned.m16n8k16.row.col.f32.bf16.bf16.f32 "            \
                 "{%0,%1,%2,%3},{%4,%5,%6,%7},{%8,%9},{%0,%1,%2,%3};"              \
                 : "+f"(c[0]), "+f"(c[1]), "+f"(c[2]), "+f"(c[3])                  \
                 : "r"(a[0]), "r"(a[1]), "r"(a[2]), "r"(a[3]),                     \
                   "r"(b[0]), "r"(b[1]))

// ---------------- tensor-core bf16 GEMM, 128x128x16 tile, 3x split, occ 2 ----
// (exact proven R8/R12 version)
template<bool NT, bool BIAS, bool CONCAT>
__global__ void __launch_bounds__(256, 2) gemm_tc(
    const float* __restrict__ A, const float* __restrict__ A2,
    const float* __restrict__ B, float* __restrict__ C,
    const float* __restrict__ bias,
    int M, int N, int K, int lda, int ldb, int ldc,
    long sA, long sB, long sC)
{
    A += (long)blockIdx.z * sA;
    B += (long)blockIdx.z * sB;
    C += (long)blockIdx.z * sC;

    __shared__ unsigned As_hi[8][136], As_lo[8][136];
    __shared__ unsigned Bs_hi[8][136], Bs_lo[8][136];

    const int tid  = threadIdx.x;
    const int lane = tid & 31;
    const int warp = tid >> 5;
    const int m0 = blockIdx.y * 128;
    const int n0 = blockIdx.x * 128;
    const int wm = (warp >> 2) * 64;
    const int wn = (warp & 3) * 32;
    const int gq = lane >> 2;
    const int tg = lane & 3;

    const int ar = tid & 127;
    const int aq = (tid >> 7) * 4;
    const int bkr = tid >> 5;
    const int bn  = (tid & 31) * 4;
    const int bn_t = tid & 127;
    const int bq   = (tid >> 7) * 4;

    float acc[4][4][4];
    #pragma unroll
    for (int i = 0; i < 4; ++i)
        #pragma unroll
        for (int j = 0; j < 4; ++j)
            #pragma unroll
            for (int q = 0; q < 4; ++q) acc[i][j][q] = 0.f;

    float4 va0, va1, vb0, vb1;
    auto load_tile = [&](int k0) {
        const float* Ab = A;
        int kc = k0;
        if (CONCAT) { if (k0 >= 256) { Ab = A2; kc = k0 - 256; } }
        va0 = *(const float4*)(Ab + (long)(m0 + ar) * lda + kc + aq);
        va1 = *(const float4*)(Ab + (long)(m0 + ar) * lda + kc + aq + 8);
        if (NT) {
            vb0 = *(const float4*)(B + (long)(n0 + bn_t) * ldb + k0 + bq);
            vb1 = *(const float4*)(B + (long)(n0 + bn_t) * ldb + k0 + bq + 8);
        } else {
            vb0 = *(const float4*)(B + (long)(k0 + 2 * bkr) * ldb + n0 + bn);
            vb1 = *(const float4*)(B + (long)(k0 + 2 * bkr + 1) * ldb + n0 + bn);
        }
    };

    load_tile(0);

    for (int k0 = 0; k0 < K; k0 += 16) {
        __syncthreads();
        {
            int kp = aq >> 1;
            split_bf2(va0.x, va0.y, As_hi[kp    ][ar], As_lo[kp    ][ar]);
            split_bf2(va0.z, va0.w, As_hi[kp + 1][ar], As_lo[kp + 1][ar]);
            split_bf2(va1.x, va1.y, As_hi[kp + 4][ar], As_lo[kp + 4][ar]);
            split_bf2(va1.z, va1.w, As_hi[kp + 5][ar], As_lo[kp + 5][ar]);
            if (NT) {
                int bp = bq >> 1;
                split_bf2(vb0.x, vb0.y, Bs_hi[bp    ][bn_t], Bs_lo[bp    ][bn_t]);
                split_bf2(vb0.z, vb0.w, Bs_hi[bp + 1][bn_t], Bs_lo[bp + 1][bn_t]);
                split_bf2(vb1.x, vb1.y, Bs_hi[bp + 4][bn_t], Bs_lo[bp + 4][bn_t]);
                split_bf2(vb1.z, vb1.w, Bs_hi[bp + 5][bn_t], Bs_lo[bp + 5][bn_t]);
            } else {
                uint4 h4, l4;
                split_bf2(vb0.x, vb1.x, h4.x, l4.x);
                split_bf2(vb0.y, vb1.y, h4.y, l4.y);
                split_bf2(vb0.z, vb1.z, h4.z, l4.z);
                split_bf2(vb0.w, vb1.w, h4.w, l4.w);
                *(uint4*)&Bs_hi[bkr][bn] = h4;
                *(uint4*)&Bs_lo[bkr][bn] = l4;
            }
        }
        __syncthreads();

        int kn = (k0 + 16 < K) ? k0 + 16 : k0;
        load_tile(kn);

        unsigned ah[4][4], al[4][4], bh[4][2], bl[4][2];
        #pragma unroll
        for (int i = 0; i < 4; ++i) {
            int r = wm + i * 16 + gq;
            ah[i][0] = As_hi[tg    ][r];
            ah[i][1] = As_hi[tg    ][r + 8];
            ah[i][2] = As_hi[tg + 4][r];
            ah[i][3] = As_hi[tg + 4][r + 8];
            al[i][0] = As_lo[tg    ][r];
            al[i][1] = As_lo[tg    ][r + 8];
            al[i][2] = As_lo[tg + 4][r];
            al[i][3] = As_lo[tg + 4][r + 8];
        }
        #pragma unroll
        for (int j = 0; j < 4; ++j) {
            int n = wn + j * 8 + gq;
            bh[j][0] = Bs_hi[tg    ][n];
            bh[j][1] = Bs_hi[tg + 4][n];
            bl[j][0] = Bs_lo[tg    ][n];
            bl[j][1] = Bs_lo[tg + 4][n];
        }
        #pragma unroll
        for (int i = 0; i < 4; ++i)
            #pragma unroll
            for (int j = 0; j < 4; ++j) {
                MMA_BF16(acc[i][j], ah[i], bh[j]);
                MMA_BF16(acc[i][j], al[i], bh[j]);
                MMA_BF16(acc[i][j], ah[i], bl[j]);
            }
    }

    #pragma unroll
    for (int i = 0; i < 4; ++i)
        #pragma unroll
        for (int j = 0; j < 4; ++j) {
            int m = m0 + wm + i * 16 + gq;
            int n = n0 + wn + j * 8 + 2 * tg;
            float2 v0 = make_float2(acc[i][j][0], acc[i][j][1]);
            float2 v1 = make_float2(acc[i][j][2], acc[i][j][3]);
            if (BIAS) {
                float b0 = bias[n], b1 = bias[n + 1];
                v0.x += b0; v0.y += b1;
                v1.x += b0; v1.y += b1;
            }
            *(float2*)(C + (long)m * ldc + n)       = v0;
            *(float2*)(C + (long)(m + 8) * ldc + n) = v1;
        }
}

// ---------------- softmax over rows of length 512 ----------
__global__ void __launch_bounds__(128) softmax_k(float* __restrict__ S)
{
    float* p = S + (long)blockIdx.x * 512;
    int tid = threadIdx.x;
    float v[4];
    float m = -1e30f;
    #pragma unroll
    for (int i = 0; i < 4; ++i) { v[i] = p[tid + 128 * i] * 0.0625f; m = fmaxf(m, v[i]); }
    __shared__ float red[128];
    red[tid] = m; __syncthreads();
    for (int s = 64; s > 0; s >>= 1) { if (tid < s) red[tid] = fmaxf(red[tid], red[tid + s]); __syncthreads(); }
    m = red[0]; __syncthreads();
    float sum = 0.f;
    #pragma unroll
    for (int i = 0; i < 4; ++i) { v[i] = __expf(v[i] - m); sum += v[i]; }
    red[tid] = sum; __syncthreads();
    for (int s = 64; s > 0; s >>= 1) { if (tid < s) red[tid] += red[tid + s]; __syncthreads(); }
    float inv = 1.f / red[0];
    #pragma unroll
    for (int i = 0; i < 4; ++i) p[tid + 128 * i] = v[i] * inv;
}

// ---------------- pack weights ----------------
// MMA col mapping within a CTA's 128 gate-cols: warp w = c>>4, local cl = c&15:
//   jl = w*4 + (cl & 3),  g = (cl >> 2) & 3   (g order f,i,u,o = Wall order)
__global__ void pack_init_k(const float* __restrict__ Wf, const float* __restrict__ Wi,
                            const float* __restrict__ Wu, const float* __restrict__ Wo,
                            const float* __restrict__ bf, const float* __restrict__ bi,
                            const float* __restrict__ bu, const float* __restrict__ bo)
{
    int idx = blockIdx.x * blockDim.x + threadIdx.x;
    int nt = gridDim.x * blockDim.x;
    // recurrent MMA weights: A = Wh^T layout [rank][c][kp] bf16 split pairs
    for (int i = idx; i < CLU * 128 * 128; i += nt) {
        int r   = i >> 14;
        int c   = (i >> 7) & 127;
        int kp  = i & 127;
        int jl  = ((c >> 4) << 2) + (c & 3);
        int g   = (c >> 2) & 3;
        int j   = r * 32 + jl;
        const float* W = (g == 0) ? Wf : (g == 1) ? Wi : (g == 2) ? Wu : Wo;
        float w0 = W[(E_ + 2 * kp) * H_ + j];
        float w1 = W[(E_ + 2 * kp + 1) * H_ + j];
        unsigned hi, lo;
        split_bf2(w0, w1, hi, lo);
        long o = (long)r * (128 * 140) + c * 140 + kp;
        g_WAh[o] = hi;
        g_WAl[o] = lo;
    }
    for (int i = idx; i < 512 * 1024; i += nt) {
        int k = i >> 10;
        int col = i & 1023;
        int g = col >> 8, j = col & 255;
        const float* W = (g == 0) ? Wf : (g == 1) ? Wi : (g == 2) ? Wu : Wo;
        float v = W[k * 256 + j];
        g_Wall[i] = v;
        if (i < 256 * 1024) g_Wfold[i] = v;
    }
    for (int i = idx; i < 1024; i += nt) {
        int g = i >> 8;
        const float* b = (g == 0) ? bf : (g == 1) ? bi : (g == 2) ? bu : bo;
        g_ball[i] = b[i & 255];
    }
}

// bfold[col] = ball[col] + sum_h bc[h] * Wall[256+h][col]
__global__ void __launch_bounds__(256) bias_fold_k(const float* __restrict__ bc)
{
    int col  = blockIdx.x * 8 + (threadIdx.x >> 5);
    int lane = threadIdx.x & 31;
    float s = 0.f;
    #pragma unroll
    for (int h = lane; h < 256; h += 32)
        s += bc[h] * g_Wall[(256 + h) * 1024 + col];
    #pragma unroll
    for (int o = 16; o > 0; o >>= 1)
        s += __shfl_xor_sync(0xffffffffu, s, o);
    if (lane == 0) g_bfold[col] = g_ball[col] + s;
}

__device__ __forceinline__ float sigf(float x)  { return 1.f / (1.f + __expf(-x)); }
__device__ __forceinline__ float tanhf_(float x){ return 2.f / (1.f + __expf(-2.f * x)) - 1.f; }

#define CARRIVE() asm volatile("barrier.cluster.arrive.aligned;" ::: "memory")
#define CWAIT()   asm volatile("barrier.cluster.wait.aligned;"   ::: "memory")

// ---------------- cluster LSTM recurrence: tensor-core mainloop ----------------
// 8 clusters x 8 CTAs, 256 threads (8 warps). Per CTA per step ONE GEMM:
//   D[128 gate-cols][8 batches] = Wh_slice^T (A, smem bf16 split) @ h (B, smem f32)
// MMA m16n8k16, M=gates N=batches K=256, 3-term bf16 split. Warp w owns rows
// w*16..w*16+15. After MMA, shfl_xor(16) pairs gate owners; each of 256 lanes
// updates exactly one (batch, jl) cell. One cluster barrier/step, no syncthreads.
__global__ void __launch_bounds__(256, 1) __cluster_dims__(CLU, 1, 1)
recur8_k(const float* __restrict__ PRE, float* __restrict__ out)
{
    extern __shared__ unsigned smu[];
    unsigned* wah = smu;                     // [128 row][140 kp]
    unsigned* wal = smu + 17920;
    float* hbuf   = (float*)(smu + 35840);   // [2 buf][256 k][12] (8 used + pad)

    const int tid  = threadIdx.x;
    const int lane = tid & 31;
    const int warp = tid >> 5;
    const int gq = lane >> 2;
    const int tg = lane & 3;
    unsigned rank;
    asm("mov.u32 %0, %%cluster_ctarank;" : "=r"(rank));
    const int bg0 = (blockIdx.x >> 3) * BGR;

    // preload this rank's Wh slice (bf16 split) + zero h buffers
    {
        const uint4* sh = (const uint4*)(g_WAh + (long)rank * 17920);
        const uint4* sl = (const uint4*)(g_WAl + (long)rank * 17920);
        uint4* dh = (uint4*)wah;
        uint4* dl = (uint4*)wal;
        for (int m = tid; m < 4480; m += 256) { dh[m] = sh[m]; dl[m] = sl[m]; }
        for (int m = tid; m < 6144; m += 256) hbuf[m] = 0.f;
    }

    // cell identity for this lane
    const int jl    = warp * 4 + (gq & 3);
    const int jg    = rank * 32 + jl;
    const int b     = 2 * tg + (gq >> 2);
    const int bglob = bg0 + b;

    float creg = 0.f, hreg = 0.f;
    float p0, p1, p2, p3;
    {
        const float* pp = PRE + (long)bglob * 1024 + jg;
        p0 = pp[0]; p1 = pp[256]; p2 = pp[512]; p3 = pp[768];
    }

    const unsigned hb_u32 = (unsigned)__cvta_generic_to_shared(hbuf);
    const unsigned* wh0 = wah + (warp * 16 + gq) * 140;
    const unsigned* wh1 = wah + (warp * 16 + gq + 8) * 140;
    const unsigned* wl0 = wal + (warp * 16 + gq) * 140;
    const unsigned* wl1 = wal + (warp * 16 + gq + 8) * 140;

    __syncthreads();
    CARRIVE(); CWAIT();

    for (int t = 0; t < T_; ++t) {
        const int buf = t & 1;
        const float* hp = hbuf + buf * 3072;

        float acc[4] = {0.f, 0.f, 0.f, 0.f};
        #pragma unroll
        for (int ks = 0; ks < 16; ++ks) {
            const int k0 = ks * 16 + tg * 2;
            float h00 = hp[(k0    ) * 12 + gq];
            float h01 = hp[(k0 + 1) * 12 + gq];
            float h10 = hp[(k0 + 8) * 12 + gq];
            float h11 = hp[(k0 + 9) * 12 + gq];
            unsigned b0h, b0l, b1h, b1l;
            split_bf2(h00, h01, b0h, b0l);
            split_bf2(h10, h11, b1h, b1l);
            const int kp = ks * 8 + tg;
            unsigned avh[4] = {wh0[kp], wh1[kp], wh0[kp + 4], wh1[kp + 4]};
            unsigned avl[4] = {wl0[kp], wl1[kp], wl0[kp + 4], wl1[kp + 4]};
            unsigned bvh[2] = {b0h, b1h};
            unsigned bvl[2] = {b0l, b1l};
            MMA_BF16(acc, avh, bvh);
            MMA_BF16(acc, avl, bvh);
            MMA_BF16(acc, avh, bvl);
        }

        // pair gate owners: lane^16 flips gq bit2 (gate g <-> g^1)
        float r0 = __shfl_xor_sync(0xffffffffu, acc[0], 16);
        float r1 = __shfl_xor_sync(0xffffffffu, acc[1], 16);
        float r2 = __shfl_xor_sync(0xffffffffu, acc[2], 16);
        float r3 = __shfl_xor_sync(0xffffffffu, acc[3], 16);
        float s0, s1, s2, s3;
        if (gq < 4) { s0 = acc[0]; s1 = r0;     s2 = acc[2]; s3 = r2;     }
        else        { s0 = r1;     s1 = acc[1]; s2 = r3;     s3 = acc[3]; }

        float fg = sigf  (s0 + p0);
        float ig = sigf  (s1 + p1);
        float ug = tanhf_(s2 + p2);
        float og = sigf  (s3 + p3);
        creg = fg * creg + ig * ug;
        hreg = og * tanhf_(creg);
        out[((long)t * B_ + bglob) * H_ + jg] = hreg;

        // publish h to all cluster CTAs' hbuf[buf^1]
        unsigned laddr = hb_u32 + ((((buf ^ 1) * 256 + jg) * 12 + b) << 2);
        #pragma unroll
        for (int rr = 0; rr < CLU; ++rr) {
            unsigned ra;
            asm volatile("mapa.shared::cluster.u32 %0, %1, %2;"
                         : "=r"(ra) : "r"(laddr), "r"(rr));
            asm volatile("st.shared::cluster.f32 [%0], %1;"
                         :: "r"(ra), "f"(hreg) : "memory");
        }

        // prefetch next step's PRE
        int tn = (t < T_ - 1) ? t + 1 : t;
        const float* pq = PRE + ((long)tn * B_ + bglob) * 1024 + jg;
        p0 = pq[0]; p1 = pq[256]; p2 = pq[512]; p3 = pq[768];

        CARRIVE();
        CWAIT();
    }

    out[(long)TB_ * H_ + bglob * H_ + jg] = hreg;                 // hx
    out[(long)TB_ * H_ + (long)B_ * H_ + bglob * H_ + jg] = creg; // cx
}

// ---------------- launch ----------------
extern "C" void kernel_launch(void* const* d_in, const int* in_sizes, int n_in,
                              void* d_out, int out_size)
{
    const float* inputs = (const float*)d_in[0];
    const float* rot    = (const float*)d_in[1];
    const float* ent    = (const float*)d_in[2];
    const float* Wf = (const float*)d_in[3];  const float* bf = (const float*)d_in[4];
    const float* Wi = (const float*)d_in[5];  const float* bi = (const float*)d_in[6];
    const float* Wu = (const float*)d_in[7];  const float* bu = (const float*)d_in[8];
    const float* Wo = (const float*)d_in[9];  const float* bo = (const float*)d_in[10];
    const float* Wc = (const float*)d_in[11]; const float* bc = (const float*)d_in[12];
    float* out = (float*)d_out;

    float *Q, *K, *S, *CTX, *PRE, *Wall, *Wfold, *bfold;
    cudaGetSymbolAddress((void**)&Q,     g_Q);
    cudaGetSymbolAddress((void**)&K,     g_K);
    cudaGetSymbolAddress((void**)&S,     g_S);
    cudaGetSymbolAddress((void**)&CTX,   g_CTX);
    cudaGetSymbolAddress((void**)&PRE,   g_PRE);
    cudaGetSymbolAddress((void**)&Wall,  g_Wall);
    cudaGetSymbolAddress((void**)&Wfold, g_Wfold);
    cudaGetSymbolAddress((void**)&bfold, g_bfold);

    const int RSMEM = 17920 * 2 * 4 + 6144 * 4;   // 167936 B
    cudaFuncSetAttribute(recur8_k, cudaFuncAttributeMaxDynamicSharedMemorySize, RSMEM);

    pack_init_k<<<256, 256>>>(Wf, Wi, Wu, Wo, bf, bi, bu, bo);
    bias_fold_k<<<128, 256>>>(bc);

    // Wfold[256:512] = Wc @ Wall[256:512]
    gemm_tc<false, false, false><<<dim3(1024 / 128, 256 / 128, 1), 256>>>(
        Wc, nullptr, Wall + 256 * 1024, Wfold + 256 * 1024, nullptr,
        256, 1024, 256, 256, 1024, 1024, 0, 0, 0);

    // Q = X @ rot ; K = X @ ent
    gemm_tc<false, false, false><<<dim3(E_ / 128, TB_ / 128, 1), 256>>>(
        inputs, nullptr, rot, Q, nullptr, TB_, E_, E_, E_, E_, E_, 0, 0, 0);
    gemm_tc<false, false, false><<<dim3(E_ / 128, TB_ / 128, 1), 256>>>(
        inputs, nullptr, ent, K, nullptr, TB_, E_, E_, E_, E_, E_, 0, 0, 0);

    // scores_b = Q_b @ K_b^T
    gemm_tc<true, false, false><<<dim3(T_ / 128, T_ / 128, B_), 256>>>(
        Q, nullptr, K, S, nullptr, T_, T_, E_, B_ * E_, B_ * E_, T_,
        (long)E_, (long)E_, (long)T_ * T_);

    softmax_k<<<B_ * T_, 128>>>(S);

    // context_b = S_b @ X_b
    gemm_tc<false, false, false><<<dim3(E_ / 128, T_ / 128, B_), 256>>>(
        S, nullptr, inputs, CTX, nullptr, T_, E_, T_, T_, B_ * E_, B_ * E_,
        (long)T_ * T_, (long)E_, (long)E_);

    // PRE = [X | CTX] @ Wfold + bfold
    gemm_tc<false, true, true><<<dim3(1024 / 128, TB_ / 128, 1), 256>>>(
        inputs, CTX, Wfold, PRE, bfold, TB_, 1024, 512, E_, 1024, 1024, 0, 0, 0);

    recur8_k<<<64, 256, RSMEM>>>(PRE, out);
    (void)in_sizes; (void)n_in; (void)out_size;
}